// round 5
// baseline (speedup 1.0000x reference)
#include <cuda_runtime.h>
#include <math.h>

// Problem constants (fixed by setup_inputs)
#define KF      16
#define TT      8
#define RRX     8
#define NBATCH  32
#define NXX     64
#define NYY     64
#define NZZ     32
#define VOX     (NXX*NYY*NZZ)     // 131072
#define OUTN    (NBATCH*VOX)      // 4194304
#define NTR     (TT*RRX)          // 64

// Device scratch (no allocations allowed)
__device__ float4       g_ypack[NTR*KF*NBATCH];   // [tr][k][n] = (yr, yi, yi, yr), 512 KB
__device__ float        g_ks[KF];
__device__ float        g_ks2[KF];
__device__ float        g_k0, g_dk;
__device__ unsigned int g_maxbits;

// ---- packed f32x2 helpers -------------------------------------------------
__device__ __forceinline__ unsigned long long pack2(float lo, float hi) {
    unsigned long long d;
    asm("mov.b64 %0, {%1, %2};" : "=l"(d) : "f"(lo), "f"(hi));
    return d;
}
__device__ __forceinline__ void unpack2(unsigned long long v, float& lo, float& hi) {
    asm("mov.b64 {%0, %1}, %2;" : "=f"(lo), "=f"(hi) : "l"(v));
}
__device__ __forceinline__ unsigned long long fma2(unsigned long long a,
                                                   unsigned long long b,
                                                   unsigned long long c) {
    unsigned long long d;
    asm("fma.rn.f32x2 %0, %1, %2, %3;" : "=l"(d) : "l"(a), "l"(b), "l"(c));
    return d;
}

// ---- Kernel 0: repack y into (yr,yi,yi,yr) tiles + wavenumber tables ------
__global__ void kirch_pack(const float* __restrict__ freqs,
                           const float* __restrict__ yre,
                           const float* __restrict__ yim) {
    int i = blockIdx.x * blockDim.x + threadIdx.x;
    const float kscale = (float)(2.0 * 3.14159265358979323846 / 299792458.0);
    if (i == 0) {
        g_maxbits = 0u;
        float k0 = kscale * freqs[0];
        float kL = kscale * freqs[KF - 1];
        g_k0 = k0;
        g_dk = (kL - k0) * (1.0f / (float)(KF - 1));
    }
    if (i < KF) {
        float kv = kscale * freqs[i];
        g_ks[i]  = kv;
        g_ks2[i] = kv * kv;
    }
    if (i < NTR * KF * NBATCH) {
        int n  = i & (NBATCH - 1);
        int kk = (i >> 5) & (KF - 1);
        int tr = i >> 9;
        int t  = tr >> 3;
        int r  = tr & 7;
        int src = ((n * KF + kk) * TT + t) * RRX + r;   // y layout (N,1,K,T,R)
        float yr = yre[src];
        float yi = yim[src];
        g_ypack[i] = make_float4(yr, yi, yi, yr);
    }
}

// ---- Kernel 1: main migration --------------------------------------------
__global__ __launch_bounds__(128)
void kirch_main(const float* __restrict__ txp, const float* __restrict__ rxp,
                const float* __restrict__ xc,  const float* __restrict__ yc,
                const float* __restrict__ zc,  float* __restrict__ out) {
    __shared__ float4 sm[KF * NBATCH];   // 8 KB, current (t,r) slice [k][n]
    __shared__ float  s_ks[KF];
    __shared__ float  s_ks2[KF];
    __shared__ float  s_pos[48];         // tx(24) then rx(24)

    const int tid = threadIdx.x;
    if (tid < KF) { s_ks[tid] = g_ks[tid]; s_ks2[tid] = g_ks2[tid]; }
    if (tid < 24) { s_pos[tid] = txp[tid]; s_pos[24 + tid] = rxp[tid]; }

    const int v  = blockIdx.x * 128 + tid;      // grid sized exactly to VOX
    const int zi = v & (NZZ - 1);
    const int yi = (v >> 5) & (NYY - 1);
    const int xi = v >> 11;
    const float px = xc[xi];
    const float py = yc[yi];
    const float pz = zc[zi];

    const float k0 = g_k0;
    const float dk = g_dk;

    __syncthreads();

    // Per-thread geometry caches: range and 2*dz/R for each tx / rx element
    float Rt[TT], Gt[TT], Rr[RRX], Gr[RRX];
#pragma unroll
    for (int t = 0; t < TT; ++t) {
        float dxv = px - s_pos[t * 3 + 0];
        float dyv = py - s_pos[t * 3 + 1];
        float dzv = pz - s_pos[t * 3 + 2];
        float r2   = dxv * dxv + dyv * dyv + dzv * dzv;
        float rinv = rsqrtf(r2);
        Rt[t] = r2 * rinv;
        Gt[t] = 2.0f * dzv * rinv;
    }
#pragma unroll
    for (int r = 0; r < RRX; ++r) {
        float dxv = px - s_pos[24 + r * 3 + 0];
        float dyv = py - s_pos[24 + r * 3 + 1];
        float dzv = pz - s_pos[24 + r * 3 + 2];
        float r2   = dxv * dxv + dyv * dyv + dzv * dzv;
        float rinv = rsqrtf(r2);
        Rr[r] = r2 * rinv;
        Gr[r] = 2.0f * dzv * rinv;
    }

    unsigned long long acc[NBATCH];
#pragma unroll
    for (int n = 0; n < NBATCH; ++n) acc[n] = 0ull;

    for (int tr = 0; tr < NTR; ++tr) {
        __syncthreads();
        const float4* src = g_ypack + tr * (KF * NBATCH);
#pragma unroll
        for (int j = 0; j < 4; ++j) sm[tid + j * 128] = src[tid + j * 128];
        __syncthreads();

        const int t = tr >> 3;
        const int r = tr & 7;
        const float Rs = Rt[t] + Rr[r];
        const float Rp = Rt[t] * Rr[r];
        const float g  = Gt[t] * Gr[r];          // = 4*dRtz*dRrz

        // exp(i*k0*Rs) with g folded in; per-k rotation by exp(i*dk*Rs)
        float s0, c0, sd, cd;
        sincosf(k0 * Rs, &s0, &c0);
        sincosf(dk * Rs, &sd, &cd);
        float er = g * c0;
        float ei = g * s0;

#pragma unroll
        for (int kk = 0; kk < KF; ++kk) {
            const float wr = fmaf(-s_ks2[kk], Rp, 1.0f);   // 1 - k^2*Rprod
            const float wi = s_ks[kk] * Rs;                // k*Rsum (exact)
            const float Ar = wr * er - wi * ei;
            const float Ai = wr * ei + wi * er;
            const unsigned long long arr = pack2(Ar, Ar);
            const unsigned long long aii = pack2(-Ai, Ai);
            const ulonglong2* yrow = (const ulonglong2*)(sm + kk * NBATCH);
#pragma unroll
            for (int n = 0; n < NBATCH; ++n) {
                ulonglong2 yv = yrow[n];       // lo=(yr,yi), hi=(yi,yr)
                acc[n] = fma2(arr, yv.x, acc[n]);
                acc[n] = fma2(aii, yv.y, acc[n]);
            }
            // advance phase: (er,ei) *= (cd,sd)
            const float ern = er * cd - ei * sd;
            ei = er * sd + ei * cd;
            er = ern;
        }
    }

    // Epilogue: magnitudes, unnormalized store, global max
    float m = 0.0f;
#pragma unroll
    for (int n = 0; n < NBATCH; ++n) {
        float xr, xim;
        unpack2(acc[n], xr, xim);
        float mag = sqrtf(xr * xr + xim * xim);
        out[n * VOX + v] = mag;
        m = fmaxf(m, mag);
    }
#pragma unroll
    for (int o = 16; o; o >>= 1)
        m = fmaxf(m, __shfl_xor_sync(0xffffffffu, m, o));
    if ((tid & 31) == 0)
        atomicMax(&g_maxbits, __float_as_uint(m));   // mags >= 0 -> bit order == value order
}

// ---- Kernel 2: normalize by global max -----------------------------------
__global__ void kirch_norm(float* __restrict__ out) {
    int i = blockIdx.x * blockDim.x + threadIdx.x;
    if (i < OUTN) {
        float inv = 1.0f / __uint_as_float(g_maxbits);
        out[i] *= inv;
    }
}

extern "C" void kernel_launch(void* const* d_in, const int* in_sizes, int n_in,
                              void* d_out, int out_size) {
    const float* freqs = (const float*)d_in[0];
    const float* txp   = (const float*)d_in[1];
    const float* rxp   = (const float*)d_in[2];
    const float* xc    = (const float*)d_in[3];
    const float* yc    = (const float*)d_in[4];
    const float* zc    = (const float*)d_in[5];
    const float* yre   = (const float*)d_in[6];
    const float* yim   = (const float*)d_in[7];
    float* out = (float*)d_out;

    kirch_pack<<<128, 256>>>(freqs, yre, yim);
    kirch_main<<<VOX / 128, 128>>>(txp, rxp, xc, yc, zc, out);
    kirch_norm<<<(OUTN + 255) / 256, 256>>>(out);
}

// round 7
// speedup vs baseline: 1.4590x; 1.4590x over previous
#include <cuda_runtime.h>
#include <math.h>

// Problem constants (fixed by setup_inputs)
#define KF      16
#define TT      8
#define RRX     8
#define NBATCH  32
#define NPAIR   (NBATCH/2)        // 16 n-pairs
#define NXX     64
#define NYY     64
#define NZZ     32
#define VOX     (NXX*NYY*NZZ)     // 131072
#define OUTN    (NBATCH*VOX)      // 4194304
#define NTR     (TT*RRX)          // 64
#define SLICE   (KF*NPAIR)        // 256 float4 per (t,r) slice = 4 KB

// Device scratch (no allocations allowed)
__device__ float4       g_ypack2[NTR*SLICE];   // [tr][k][p] = (yr_2p, yr_2p+1, yi_2p, yi_2p+1), 256 KB
__device__ float        g_k0, g_dk;
__device__ unsigned int g_maxbits;

// ---- packed f32x2 helpers -------------------------------------------------
__device__ __forceinline__ unsigned long long pack2(float lo, float hi) {
    unsigned long long d;
    asm("mov.b64 %0, {%1, %2};" : "=l"(d) : "f"(lo), "f"(hi));
    return d;
}
__device__ __forceinline__ void unpack2(unsigned long long v, float& lo, float& hi) {
    asm("mov.b64 {%0, %1}, %2;" : "=f"(lo), "=f"(hi) : "l"(v));
}
__device__ __forceinline__ unsigned long long fma2(unsigned long long a,
                                                   unsigned long long b,
                                                   unsigned long long c) {
    unsigned long long d;
    asm("fma.rn.f32x2 %0, %1, %2, %3;" : "=l"(d) : "l"(a), "l"(b), "l"(c));
    return d;
}

// ---- Kernel 0: repack y into SoA n-pair tiles + wavenumber seeds ----------
__global__ void kirch_pack(const float* __restrict__ freqs,
                           const float* __restrict__ yre,
                           const float* __restrict__ yim) {
    int i = blockIdx.x * blockDim.x + threadIdx.x;
    const float kscale = (float)(2.0 * 3.14159265358979323846 / 299792458.0);
    if (i == 0) {
        g_maxbits = 0u;
        float k0 = kscale * freqs[0];
        float kL = kscale * freqs[KF - 1];
        g_k0 = k0;
        g_dk = (kL - k0) * (1.0f / (float)(KF - 1));
    }
    if (i < NTR * SLICE) {
        int p  = i & (NPAIR - 1);
        int kk = (i >> 4) & (KF - 1);
        int tr = i >> 8;
        int t  = tr >> 3;
        int r  = tr & 7;
        int n0 = 2 * p;
        int s0 = ((n0 * KF + kk) * TT + t) * RRX + r;         // y layout (N,1,K,T,R)
        int s1 = (((n0 + 1) * KF + kk) * TT + t) * RRX + r;
        g_ypack2[i] = make_float4(yre[s0], yre[s1], yim[s0], yim[s1]);
    }
}

// ---- Kernel 1: main migration --------------------------------------------
__global__ __launch_bounds__(128)
void kirch_main(const float* __restrict__ txp, const float* __restrict__ rxp,
                const float* __restrict__ xc,  const float* __restrict__ yc,
                const float* __restrict__ zc,  float* __restrict__ out) {
    __shared__ float4 sm[2][SLICE];      // double-buffered (t,r) slice, 8 KB
    __shared__ float  s_pos[48];         // tx(24) then rx(24)

    const int tid = threadIdx.x;
    if (tid < 24) { s_pos[tid] = txp[tid]; s_pos[24 + tid] = rxp[tid]; }

    const int v  = blockIdx.x * 128 + tid;      // grid sized exactly to VOX
    const int zi = v & (NZZ - 1);
    const int yi = (v >> 5) & (NYY - 1);
    const int xi = v >> 11;
    const float px = xc[xi];
    const float py = yc[yi];
    const float pz = zc[zi];

    const float k0  = g_k0;
    const float dk  = g_dk;
    const float k0sq = k0 * k0;
    const float c1   = dk * (2.0f * k0 + dk);   // wr second-order recurrence seeds
    const float c2   = 2.0f * dk * dk;

    // preload slice 0
    {
        float4 a = g_ypack2[tid];
        float4 b = g_ypack2[tid + 128];
        sm[0][tid] = a;
        sm[0][tid + 128] = b;
    }
    __syncthreads();

    // Persistent rx geometry (tx recomputed per t — saves registers)
    float Rr[RRX], Gr[RRX];
#pragma unroll
    for (int r = 0; r < RRX; ++r) {
        float dxv = px - s_pos[24 + r * 3 + 0];
        float dyv = py - s_pos[24 + r * 3 + 1];
        float dzv = pz - s_pos[24 + r * 3 + 2];
        float r2   = dxv * dxv + dyv * dyv + dzv * dzv;
        float rinv = rsqrtf(r2);
        Rr[r] = r2 * rinv;
        Gr[r] = 2.0f * dzv * rinv;
    }

    unsigned long long accr[NPAIR], acci[NPAIR];
#pragma unroll
    for (int p = 0; p < NPAIR; ++p) { accr[p] = 0ull; acci[p] = 0ull; }

    float Rt = 0.0f, Gt = 0.0f;
    for (int tr = 0; tr < NTR; ++tr) {
        const int buf = tr & 1;
        float4 pf0, pf1;
        const bool more = (tr + 1 < NTR);
        if (more) {                                   // prefetch next slice
            pf0 = g_ypack2[(tr + 1) * SLICE + tid];
            pf1 = g_ypack2[(tr + 1) * SLICE + tid + 128];
        }
        if ((tr & 7) == 0) {                          // new tx element
            int t = tr >> 3;
            float dxv = px - s_pos[t * 3 + 0];
            float dyv = py - s_pos[t * 3 + 1];
            float dzv = pz - s_pos[t * 3 + 2];
            float r2   = dxv * dxv + dyv * dyv + dzv * dzv;
            float rinv = rsqrtf(r2);
            Rt = r2 * rinv;
            Gt = 2.0f * dzv * rinv;
        }
        const int r = tr & 7;
        const float Rs = Rt + Rr[r];
        const float Rp = Rt * Rr[r];
        const float g  = Gt * Gr[r];                  // = 4*dRtz*dRrz

        // exp(i*k0*Rs) with g folded in; per-k rotation by exp(i*dk*Rs)
        float s0, c0, sd, cd;
        sincosf(k0 * Rs, &s0, &c0);
        sincosf(dk * Rs, &sd, &cd);
        float er = g * c0;
        float ei = g * s0;

        // exact polynomial terms via recurrences:
        //   wi_j = k_j*Rs         -> wi += dk*Rs
        //   wr_j = 1 - k_j^2*Rp   -> wr += del; del += cc   (2nd-order, exact)
        float wi  = k0 * Rs;
        float wr  = fmaf(-k0sq, Rp, 1.0f);
        const float dwi = dk * Rs;
        float del = -Rp * c1;
        const float cc  = -Rp * c2;

        const ulonglong2* row = (const ulonglong2*)sm[buf];
#pragma unroll
        for (int kk = 0; kk < KF; ++kk) {
            const float t1 = wi * ei;
            const float Ar = fmaf(wr, er, -t1);
            const float t2 = wi * er;
            const float Ai = fmaf(wr, ei,  t2);
            const unsigned long long Ar2  = pack2(Ar,  Ar);
            const unsigned long long Ai2  = pack2(Ai,  Ai);
            const unsigned long long mAi2 = pack2(-Ai, -Ai);
            const ulonglong2* yrow = row + kk * NPAIR;
#pragma unroll
            for (int c = 0; c < 4; ++c) {
                const ulonglong2 v0 = yrow[4 * c + 0];
                const ulonglong2 v1 = yrow[4 * c + 1];
                const ulonglong2 v2 = yrow[4 * c + 2];
                const ulonglong2 v3 = yrow[4 * c + 3];
                // grouped by A operand so ptxas can .reuse the broadcast pair
                accr[4 * c + 0] = fma2(Ar2,  v0.x, accr[4 * c + 0]);
                accr[4 * c + 1] = fma2(Ar2,  v1.x, accr[4 * c + 1]);
                accr[4 * c + 2] = fma2(Ar2,  v2.x, accr[4 * c + 2]);
                accr[4 * c + 3] = fma2(Ar2,  v3.x, accr[4 * c + 3]);
                acci[4 * c + 0] = fma2(Ai2,  v0.x, acci[4 * c + 0]);
                acci[4 * c + 1] = fma2(Ai2,  v1.x, acci[4 * c + 1]);
                acci[4 * c + 2] = fma2(Ai2,  v2.x, acci[4 * c + 2]);
                acci[4 * c + 3] = fma2(Ai2,  v3.x, acci[4 * c + 3]);
                accr[4 * c + 0] = fma2(mAi2, v0.y, accr[4 * c + 0]);
                accr[4 * c + 1] = fma2(mAi2, v1.y, accr[4 * c + 1]);
                accr[4 * c + 2] = fma2(mAi2, v2.y, accr[4 * c + 2]);
                accr[4 * c + 3] = fma2(mAi2, v3.y, accr[4 * c + 3]);
                acci[4 * c + 0] = fma2(Ar2,  v0.y, acci[4 * c + 0]);
                acci[4 * c + 1] = fma2(Ar2,  v1.y, acci[4 * c + 1]);
                acci[4 * c + 2] = fma2(Ar2,  v2.y, acci[4 * c + 2]);
                acci[4 * c + 3] = fma2(Ar2,  v3.y, acci[4 * c + 3]);
            }
            // advance phase: (er,ei) *= (cd,sd); advance polynomial terms
            const float ern = fmaf(er, cd, -(ei * sd));
            ei = fmaf(er, sd, ei * cd);
            er = ern;
            wi += dwi;
            wr += del;
            del += cc;
        }

        if (more) {
            sm[buf ^ 1][tid]       = pf0;
            sm[buf ^ 1][tid + 128] = pf1;
        }
        __syncthreads();
    }

    // Epilogue: magnitudes, unnormalized store, global max
    float m = 0.0f;
#pragma unroll
    for (int p = 0; p < NPAIR; ++p) {
        float a0, a1, b0, b1;
        unpack2(accr[p], a0, a1);
        unpack2(acci[p], b0, b1);
        float m0 = sqrtf(a0 * a0 + b0 * b0);
        float m1 = sqrtf(a1 * a1 + b1 * b1);
        out[(2 * p + 0) * VOX + v] = m0;
        out[(2 * p + 1) * VOX + v] = m1;
        m = fmaxf(m, fmaxf(m0, m1));
    }
#pragma unroll
    for (int o = 16; o; o >>= 1)
        m = fmaxf(m, __shfl_xor_sync(0xffffffffu, m, o));
    if ((tid & 31) == 0)
        atomicMax(&g_maxbits, __float_as_uint(m));   // mags >= 0 -> bit order == value order
}

// ---- Kernel 2: normalize by global max -----------------------------------
__global__ void kirch_norm(float* __restrict__ out) {
    int i = blockIdx.x * blockDim.x + threadIdx.x;
    if (i < OUTN) {
        float inv = 1.0f / __uint_as_float(g_maxbits);
        out[i] *= inv;
    }
}

extern "C" void kernel_launch(void* const* d_in, const int* in_sizes, int n_in,
                              void* d_out, int out_size) {
    const float* freqs = (const float*)d_in[0];
    const float* txp   = (const float*)d_in[1];
    const float* rxp   = (const float*)d_in[2];
    const float* xc    = (const float*)d_in[3];
    const float* yc    = (const float*)d_in[4];
    const float* zc    = (const float*)d_in[5];
    const float* yre   = (const float*)d_in[6];
    const float* yim   = (const float*)d_in[7];
    float* out = (float*)d_out;

    kirch_pack<<<64, 256>>>(freqs, yre, yim);
    kirch_main<<<VOX / 128, 128>>>(txp, rxp, xc, yc, zc, out);
    kirch_norm<<<(OUTN + 255) / 256, 256>>>(out);
}